// round 1
// baseline (speedup 1.0000x reference)
#include <cuda_runtime.h>
#include <cuda_bf16.h>
#include <cstdint>

// ---------------------------------------------------------------------------
// Problem constants
// ---------------------------------------------------------------------------
#define NW        192           // number of windows per image
#define BWIN      1536          // B_ = 8 * 192 windows total
#define NTOK      64            // tokens per window
#define DIMC      192           // channels
#define HEADS     6
#define HDIM      32
#define M_TOT     (BWIN * NTOK) // 98304 rows

// scratch (static device globals: allocation-free)
__device__ float g_Q [M_TOT * DIMC];       // 75.5 MB
__device__ float g_KV[M_TOT * 2 * DIMC];   // 151 MB
__device__ float g_O [M_TOT * DIMC];       // 75.5 MB

// ---------------------------------------------------------------------------
// packed f32x2 helpers (FFMA2 — 2x fp32 throughput on sm_103a)
// ---------------------------------------------------------------------------
__device__ __forceinline__ unsigned long long ffma2(unsigned long long a,
                                                    unsigned long long b,
                                                    unsigned long long c) {
    unsigned long long d;
    asm("fma.rn.f32x2 %0, %1, %2, %3;" : "=l"(d) : "l"(a), "l"(b), "l"(c));
    return d;
}
__device__ __forceinline__ unsigned long long pack2(float x, float y) {
    unsigned long long r;
    asm("mov.b64 %0, {%1, %2};" : "=l"(r) : "f"(x), "f"(y));
    return r;
}
__device__ __forceinline__ float u64lo(unsigned long long v) {
    return __uint_as_float((unsigned int)v);
}
__device__ __forceinline__ float u64hi(unsigned long long v) {
    return __uint_as_float((unsigned int)(v >> 32));
}

// ---------------------------------------------------------------------------
// GEMM: Y[M,N] = A[M,K] @ W[N,K]^T + bias[N]
// block tile 128(M) x 64(N), 256 threads, thread tile 8x4, K-chunk 16.
// Inner product in packed fma.rn.f32x2.
// ---------------------------------------------------------------------------
__global__ void __launch_bounds__(256)
gemm_bias_kernel(const float* __restrict__ A, const float* __restrict__ W,
                 const float* __restrict__ bias, float* __restrict__ Y,
                 int N, int K)
{
    __shared__ __align__(16) float Ask[16][132];  // k-major A tile (128 rows)
    __shared__ __align__(16) float Bsk[16][68];   // k-major W tile (64 rows)

    const int tid = threadIdx.x;
    const int tx  = tid & 15;   // n direction (4 cols each)
    const int ty  = tid >> 4;   // m direction (8 rows each)
    const int m0  = blockIdx.y * 128;
    const int n0  = blockIdx.x * 64;
    const int lr  = tid >> 2;   // 0..63 (load row)
    const int lq  = tid & 3;    // 0..3  (load k-quad)

    const float* Aptr0 = A + (size_t)(m0 + lr) * K + lq * 4;
    const float* Aptr1 = Aptr0 + (size_t)64 * K;
    const float* Wptr  = W + (size_t)(n0 + lr) * K + lq * 4;

    float4 a0 = *(const float4*)Aptr0;
    float4 a1 = *(const float4*)Aptr1;
    float4 b0 = *(const float4*)Wptr;

    unsigned long long acc[4][4];
#pragma unroll
    for (int p = 0; p < 4; p++)
#pragma unroll
        for (int j = 0; j < 4; j++) acc[p][j] = 0ull;

    const int NCH = K / 16;     // 12
    for (int ch = 0; ch < NCH; ch++) {
        __syncthreads();
        Ask[lq * 4 + 0][lr]      = a0.x;
        Ask[lq * 4 + 1][lr]      = a0.y;
        Ask[lq * 4 + 2][lr]      = a0.z;
        Ask[lq * 4 + 3][lr]      = a0.w;
        Ask[lq * 4 + 0][lr + 64] = a1.x;
        Ask[lq * 4 + 1][lr + 64] = a1.y;
        Ask[lq * 4 + 2][lr + 64] = a1.z;
        Ask[lq * 4 + 3][lr + 64] = a1.w;
        Bsk[lq * 4 + 0][lr]      = b0.x;
        Bsk[lq * 4 + 1][lr]      = b0.y;
        Bsk[lq * 4 + 2][lr]      = b0.z;
        Bsk[lq * 4 + 3][lr]      = b0.w;
        __syncthreads();

        if (ch + 1 < NCH) {      // prefetch next chunk while computing
            a0 = *(const float4*)(Aptr0 + (ch + 1) * 16);
            a1 = *(const float4*)(Aptr1 + (ch + 1) * 16);
            b0 = *(const float4*)(Wptr  + (ch + 1) * 16);
        }

#pragma unroll
        for (int kk = 0; kk < 16; kk++) {
            double2 dA = *(const double2*)&Ask[kk][ty * 8];
            double2 dB = *(const double2*)&Ask[kk][ty * 8 + 4];
            float4  bv = *(const float4*)&Bsk[kk][tx * 4];
            unsigned long long ap[4];
            ap[0] = (unsigned long long)__double_as_longlong(dA.x);
            ap[1] = (unsigned long long)__double_as_longlong(dA.y);
            ap[2] = (unsigned long long)__double_as_longlong(dB.x);
            ap[3] = (unsigned long long)__double_as_longlong(dB.y);
            unsigned long long bp[4];
            bp[0] = pack2(bv.x, bv.x);
            bp[1] = pack2(bv.y, bv.y);
            bp[2] = pack2(bv.z, bv.z);
            bp[3] = pack2(bv.w, bv.w);
#pragma unroll
            for (int p = 0; p < 4; p++)
#pragma unroll
                for (int j = 0; j < 4; j++)
                    acc[p][j] = ffma2(ap[p], bp[j], acc[p][j]);
        }
    }

    // epilogue: add bias, store two rows per packed pair
    float4 bvec = *(const float4*)&bias[n0 + tx * 4];
#pragma unroll
    for (int p = 0; p < 4; p++) {
        float4 r0, r1;
        r0.x = u64lo(acc[p][0]) + bvec.x;  r1.x = u64hi(acc[p][0]) + bvec.x;
        r0.y = u64lo(acc[p][1]) + bvec.y;  r1.y = u64hi(acc[p][1]) + bvec.y;
        r0.z = u64lo(acc[p][2]) + bvec.z;  r1.z = u64hi(acc[p][2]) + bvec.z;
        r0.w = u64lo(acc[p][3]) + bvec.w;  r1.w = u64hi(acc[p][3]) + bvec.w;
        int m = m0 + ty * 8 + p * 2;
        *(float4*)&Y[(size_t)m       * N + n0 + tx * 4] = r0;
        *(float4*)&Y[(size_t)(m + 1) * N + n0 + tx * 4] = r1;
    }
}

// ---------------------------------------------------------------------------
// Fused windowed attention: one block per (head, window).
// S = (Q*scale) K^T + rpb[rpi] + mask  ->  softmax  ->  O = P V
// ---------------------------------------------------------------------------
__global__ void __launch_bounds__(256)
attn_kernel(const float* __restrict__ Q, const float* __restrict__ KV,
            const float* __restrict__ mask, const int* __restrict__ rpi,
            const float* __restrict__ rpb, float* __restrict__ O)
{
    const int h = blockIdx.x;          // head 0..5
    const int b = blockIdx.y;          // window 0..1535
    const int w = b % NW;              // shift-mask window id

    __shared__ float Qs[64][33];
    __shared__ float Ks[64][33];
    __shared__ float Vs[64][33];
    __shared__ float Add[64 * 64];     // rpb + mask, flat [n*64+m]
    __shared__ float Ps[8][64];        // per-warp probability row

    const int tid = threadIdx.x;

    // ---- load Q,K,V tiles (scaled Q) ----
    {
        const int n = tid >> 2;        // token row
        const int q = tid & 3;         // 8-float segment
        const float scale = 0.17677669529663687f;   // 1/sqrt(32)

        const float* qrow = Q + ((size_t)(b * 64 + n)) * DIMC + h * HDIM + q * 8;
        float4 v0 = *(const float4*)qrow;
        float4 v1 = *(const float4*)(qrow + 4);
        Qs[n][q * 8 + 0] = v0.x * scale;  Qs[n][q * 8 + 1] = v0.y * scale;
        Qs[n][q * 8 + 2] = v0.z * scale;  Qs[n][q * 8 + 3] = v0.w * scale;
        Qs[n][q * 8 + 4] = v1.x * scale;  Qs[n][q * 8 + 5] = v1.y * scale;
        Qs[n][q * 8 + 6] = v1.z * scale;  Qs[n][q * 8 + 7] = v1.w * scale;

        const float* krow = KV + ((size_t)(b * 64 + n)) * (2 * DIMC) + h * HDIM + q * 8;
        v0 = *(const float4*)krow;
        v1 = *(const float4*)(krow + 4);
        Ks[n][q * 8 + 0] = v0.x;  Ks[n][q * 8 + 1] = v0.y;
        Ks[n][q * 8 + 2] = v0.z;  Ks[n][q * 8 + 3] = v0.w;
        Ks[n][q * 8 + 4] = v1.x;  Ks[n][q * 8 + 5] = v1.y;
        Ks[n][q * 8 + 6] = v1.z;  Ks[n][q * 8 + 7] = v1.w;

        const float* vrow = krow + DIMC;
        v0 = *(const float4*)vrow;
        v1 = *(const float4*)(vrow + 4);
        Vs[n][q * 8 + 0] = v0.x;  Vs[n][q * 8 + 1] = v0.y;
        Vs[n][q * 8 + 2] = v0.z;  Vs[n][q * 8 + 3] = v0.w;
        Vs[n][q * 8 + 4] = v1.x;  Vs[n][q * 8 + 5] = v1.y;
        Vs[n][q * 8 + 6] = v1.z;  Vs[n][q * 8 + 7] = v1.w;
    }

    // ---- precombine relative-position bias + shift mask ----
    {
        const float* mbase = mask + (size_t)w * 4096;
#pragma unroll
        for (int i = tid; i < 4096; i += 256) {
            int idx = rpi[i];
            Add[i] = rpb[idx * HEADS + h] + mbase[i];
        }
    }
    __syncthreads();

    const int warp = tid >> 5;
    const int lane = tid & 31;

    for (int r = 0; r < 8; r++) {
        const int n = warp * 8 + r;

        // S row: lane covers columns (lane, lane+32)
        float s0 = 0.f, s1 = 0.f;
#pragma unroll
        for (int d = 0; d < 32; d++) {
            float qv = Qs[n][d];
            s0 = fmaf(qv, Ks[lane][d],      s0);
            s1 = fmaf(qv, Ks[lane + 32][d], s1);
        }
        s0 += Add[n * 64 + lane];
        s1 += Add[n * 64 + lane + 32];

        // softmax over 64 cols
        float mx = fmaxf(s0, s1);
#pragma unroll
        for (int o = 16; o; o >>= 1) mx = fmaxf(mx, __shfl_xor_sync(0xffffffffu, mx, o));
        float e0 = __expf(s0 - mx);
        float e1 = __expf(s1 - mx);
        float sum = e0 + e1;
#pragma unroll
        for (int o = 16; o; o >>= 1) sum += __shfl_xor_sync(0xffffffffu, sum, o);
        float inv = 1.0f / sum;

        Ps[warp][lane]      = e0 * inv;
        Ps[warp][lane + 32] = e1 * inv;
        __syncwarp();

        // O row: lane = output dim dd
        float o = 0.f;
#pragma unroll
        for (int m = 0; m < 64; m++)
            o = fmaf(Ps[warp][m], Vs[m][lane], o);

        O[((size_t)(b * 64 + n)) * DIMC + h * HDIM + lane] = o;
        __syncwarp();
    }
}

// ---------------------------------------------------------------------------
// launcher
// ---------------------------------------------------------------------------
extern "C" void kernel_launch(void* const* d_in, const int* in_sizes, int n_in,
                              void* d_out, int out_size)
{
    const float* x    = (const float*)d_in[0];
    const float* px   = (const float*)d_in[1];
    const float* mask = (const float*)d_in[2];
    const int*   rpi  = (const int*)  d_in[3];
    const float* rpb  = (const float*)d_in[4];
    const float* wq   = (const float*)d_in[5];
    const float* bq   = (const float*)d_in[6];
    const float* wkv  = (const float*)d_in[7];
    const float* bkv  = (const float*)d_in[8];
    const float* wp   = (const float*)d_in[9];
    const float* bp   = (const float*)d_in[10];
    float* out = (float*)d_out;

    float *qbuf, *kvbuf, *obuf;
    cudaGetSymbolAddress((void**)&qbuf,  g_Q);
    cudaGetSymbolAddress((void**)&kvbuf, g_KV);
    cudaGetSymbolAddress((void**)&obuf,  g_O);

    const int MB = M_TOT / 128;   // 768 row-tiles

    // Q = x @ wq^T + bq
    gemm_bias_kernel<<<dim3(DIMC / 64, MB), 256>>>(x, wq, bq, qbuf, DIMC, DIMC);
    // KV = partial_x @ wkv^T + bkv
    gemm_bias_kernel<<<dim3(2 * DIMC / 64, MB), 256>>>(px, wkv, bkv, kvbuf, 2 * DIMC, DIMC);
    // fused windowed attention
    attn_kernel<<<dim3(HEADS, BWIN), 256>>>(qbuf, kvbuf, mask, rpi, rpb, obuf);
    // out = attn_out @ wp^T + bp
    gemm_bias_kernel<<<dim3(DIMC / 64, MB), 256>>>(obuf, wp, bp, out, DIMC, DIMC);
}

// round 3
// speedup vs baseline: 1.2765x; 1.2765x over previous
#include <cuda_runtime.h>
#include <cuda_bf16.h>
#include <cstdint>

// ---------------------------------------------------------------------------
// Problem constants
// ---------------------------------------------------------------------------
#define NW        192
#define BWIN      1536
#define NTOK      64
#define DIMC      192
#define HEADS     6
#define HDIM      32
#define M_TOT     (BWIN * NTOK)     // 98304
#define MTILES    (M_TOT / 128)     // 768

// scratch
__device__ float g_Q [M_TOT * DIMC];
__device__ float g_KV[M_TOT * 2 * DIMC];
__device__ float g_O [M_TOT * DIMC];

// ---------------------------------------------------------------------------
// helpers
// ---------------------------------------------------------------------------
__device__ __forceinline__ unsigned long long ffma2(unsigned long long a,
                                                    unsigned long long b,
                                                    unsigned long long c) {
    unsigned long long d;
    asm("fma.rn.f32x2 %0, %1, %2, %3;" : "=l"(d) : "l"(a), "l"(b), "l"(c));
    return d;
}
__device__ __forceinline__ float u64lo(unsigned long long v) {
    return __uint_as_float((unsigned int)v);
}
__device__ __forceinline__ float u64hi(unsigned long long v) {
    return __uint_as_float((unsigned int)(v >> 32));
}

// fp32 -> bf16 hi/lo split of 4 consecutive values -> two packed uint2
__device__ __forceinline__ void split4(float4 v, uint2& hi, uint2& lo) {
    __nv_bfloat16 h0 = __float2bfloat16_rn(v.x);
    __nv_bfloat16 h1 = __float2bfloat16_rn(v.y);
    __nv_bfloat16 h2 = __float2bfloat16_rn(v.z);
    __nv_bfloat16 h3 = __float2bfloat16_rn(v.w);
    __nv_bfloat16 l0 = __float2bfloat16_rn(v.x - __bfloat162float(h0));
    __nv_bfloat16 l1 = __float2bfloat16_rn(v.y - __bfloat162float(h1));
    __nv_bfloat16 l2 = __float2bfloat16_rn(v.z - __bfloat162float(h2));
    __nv_bfloat16 l3 = __float2bfloat16_rn(v.w - __bfloat162float(h3));
    union { __nv_bfloat162 b; uint32_t u; } c0, c1, c2, c3;
    c0.b = __halves2bfloat162(h0, h1);  c1.b = __halves2bfloat162(h2, h3);
    c2.b = __halves2bfloat162(l0, l1);  c3.b = __halves2bfloat162(l2, l3);
    hi.x = c0.u; hi.y = c1.u;
    lo.x = c2.u; lo.y = c3.u;
}

// mma.sync m16n8k16 row.col f32 += bf16*bf16  (base-target tensor path)
__device__ __forceinline__ void hmma(float* d, const uint32_t* a,
                                     uint32_t b0, uint32_t b1) {
    asm volatile(
        "mma.sync.aligned.m16n8k16.row.col.f32.bf16.bf16.f32 "
        "{%0,%1,%2,%3}, {%4,%5,%6,%7}, {%8,%9}, {%0,%1,%2,%3};"
        : "+f"(d[0]), "+f"(d[1]), "+f"(d[2]), "+f"(d[3])
        : "r"(a[0]), "r"(a[1]), "r"(a[2]), "r"(a[3]), "r"(b0), "r"(b1));
}

// ---------------------------------------------------------------------------
// HMMA GEMM: Y[M,192] = A[M,192] @ W[192,192]^T + bias   (bf16x3 split)
// persistent CTAs, M-tile 128xN192, W resident in smem as bf16 hi/lo.
// ---------------------------------------------------------------------------
#define WSTRIDE 200      // bf16 elems per W smem row (conflict-free)
#define ASTRIDE 104      // bf16 elems per A smem row (chunk K=96)

#define SM_WHI   0
#define SM_WLO   (SM_WHI + 192 * WSTRIDE * 2)        // 76800
#define SM_AHI   (SM_WLO + 192 * WSTRIDE * 2)        // 153600
#define SM_ALO   (SM_AHI + 128 * ASTRIDE * 2)        // 180224
#define SM_BIAS  (SM_ALO + 128 * ASTRIDE * 2)        // 206848
#define SM_TOTAL (SM_BIAS + 192 * 4)                 // 207616

__global__ void __launch_bounds__(256, 1)
gemm_hmma_kernel(const float* __restrict__ A, const float* __restrict__ W,
                 const float* __restrict__ bias, float* __restrict__ Y, int ldY)
{
    extern __shared__ char smem[];
    __nv_bfloat16* whi = (__nv_bfloat16*)(smem + SM_WHI);
    __nv_bfloat16* wlo = (__nv_bfloat16*)(smem + SM_WLO);
    __nv_bfloat16* ahi = (__nv_bfloat16*)(smem + SM_AHI);
    __nv_bfloat16* alo = (__nv_bfloat16*)(smem + SM_ALO);
    float*         bss = (float*)       (smem + SM_BIAS);

    const int tid  = threadIdx.x;
    const int lane = tid & 31;
    const int warp = tid >> 5;
    const int wm   = warp >> 1;              // 0..3 (M)
    const int wn   = warp & 1;               // 0..1 (N)

    // ---- convert W (192x192 fp32) to bf16 hi/lo in smem, once ----
    for (int i = tid; i < 192 * 48; i += 256) {
        int row = i / 48;
        int k4  = (i % 48) * 4;
        float4 v = *(const float4*)(W + (size_t)row * DIMC + k4);
        uint2 hi, lo; split4(v, hi, lo);
        *(uint2*)(whi + row * WSTRIDE + k4) = hi;
        *(uint2*)(wlo + row * WSTRIDE + k4) = lo;
    }
    if (tid < DIMC) bss[tid] = bias[tid];
    __syncthreads();

    const int fr = lane >> 2;                // fragment row/col group
    const int fc = (lane & 3) * 2;           // fragment k pair

    for (int tile = blockIdx.x; tile < MTILES; tile += gridDim.x) {
        float acc[2][12][4];
#pragma unroll
        for (int mi = 0; mi < 2; mi++)
#pragma unroll
            for (int nt = 0; nt < 12; nt++)
#pragma unroll
                for (int j = 0; j < 4; j++) acc[mi][nt][j] = 0.f;

#pragma unroll 1
        for (int c = 0; c < 2; c++) {
            __syncthreads();
            // load + convert A chunk: 128 rows x 96 cols (fp32 -> bf16 hi/lo)
            for (int i = tid; i < 128 * 24; i += 256) {
                int row = i / 24;
                int c4  = (i % 24) * 4;
                float4 v = *(const float4*)(A + (size_t)(tile * 128 + row) * DIMC
                                              + c * 96 + c4);
                uint2 hi, lo; split4(v, hi, lo);
                *(uint2*)(ahi + row * ASTRIDE + c4) = hi;
                *(uint2*)(alo + row * ASTRIDE + c4) = lo;
            }
            __syncthreads();

#pragma unroll
            for (int ks = 0; ks < 6; ks++) {
                const int kk = ks * 16;
                // A fragments for both 16-row tiles (hi and lo versions)
                uint32_t fa_hi[2][4], fa_lo[2][4];
#pragma unroll
                for (int mi = 0; mi < 2; mi++) {
                    int r0 = wm * 32 + mi * 16 + fr;
                    const char* bh = (const char*)ahi;
                    const char* bl = (const char*)alo;
                    uint32_t o00 = (uint32_t)((r0     * ASTRIDE + kk + fc    ) * 2);
                    uint32_t o10 = (uint32_t)(((r0+8) * ASTRIDE + kk + fc    ) * 2);
                    uint32_t o01 = (uint32_t)((r0     * ASTRIDE + kk + fc + 8) * 2);
                    uint32_t o11 = (uint32_t)(((r0+8) * ASTRIDE + kk + fc + 8) * 2);
                    fa_hi[mi][0] = *(const uint32_t*)(bh + o00);
                    fa_hi[mi][1] = *(const uint32_t*)(bh + o10);
                    fa_hi[mi][2] = *(const uint32_t*)(bh + o01);
                    fa_hi[mi][3] = *(const uint32_t*)(bh + o11);
                    fa_lo[mi][0] = *(const uint32_t*)(bl + o00);
                    fa_lo[mi][1] = *(const uint32_t*)(bl + o10);
                    fa_lo[mi][2] = *(const uint32_t*)(bl + o01);
                    fa_lo[mi][3] = *(const uint32_t*)(bl + o11);
                }
                const int kg = c * 96 + kk + fc;
#pragma unroll
                for (int nt = 0; nt < 12; nt++) {
                    int nrow = wn * 96 + nt * 8 + fr;
                    uint32_t ob0 = (uint32_t)((nrow * WSTRIDE + kg    ) * 2);
                    uint32_t ob1 = (uint32_t)((nrow * WSTRIDE + kg + 8) * 2);
                    uint32_t bh0 = *(const uint32_t*)((const char*)whi + ob0);
                    uint32_t bh1 = *(const uint32_t*)((const char*)whi + ob1);
                    uint32_t bl0 = *(const uint32_t*)((const char*)wlo + ob0);
                    uint32_t bl1 = *(const uint32_t*)((const char*)wlo + ob1);
#pragma unroll
                    for (int mi = 0; mi < 2; mi++) {
                        hmma(acc[mi][nt], fa_hi[mi], bh0, bh1);
                        hmma(acc[mi][nt], fa_lo[mi], bh0, bh1);
                        hmma(acc[mi][nt], fa_hi[mi], bl0, bl1);
                    }
                }
            }
        }

        // ---- epilogue: bias add + store ----
#pragma unroll
        for (int mi = 0; mi < 2; mi++) {
            int row = tile * 128 + wm * 32 + mi * 16 + fr;
#pragma unroll
            for (int nt = 0; nt < 12; nt++) {
                int col = wn * 96 + nt * 8 + fc;
                float2 bv = *(const float2*)&bss[col];
                float2 r0, r1;
                r0.x = acc[mi][nt][0] + bv.x;  r0.y = acc[mi][nt][1] + bv.y;
                r1.x = acc[mi][nt][2] + bv.x;  r1.y = acc[mi][nt][3] + bv.y;
                *(float2*)&Y[(size_t)row       * ldY + col] = r0;
                *(float2*)&Y[(size_t)(row + 8) * ldY + col] = r1;
            }
        }
    }
}

// ---------------------------------------------------------------------------
// Fused windowed attention (fp32, packed FFMA2, transposed V)
// ---------------------------------------------------------------------------
__global__ void __launch_bounds__(256)
attn_kernel(const float* __restrict__ Q, const float* __restrict__ KV,
            const float* __restrict__ mask, const int* __restrict__ rpi,
            const float* __restrict__ rpb, float* __restrict__ O)
{
    const int h = blockIdx.x;
    const int b = blockIdx.y;
    const int w = b % NW;

    __shared__ float Qs[64][36];
    __shared__ float Ks[64][36];
    __shared__ float Vt[32][68];
    __shared__ float Add[4096];
    __shared__ float Ps[8][64];

    const int tid = threadIdx.x;

    {
        const int n = tid >> 2;
        const int q = tid & 3;
        const float scale = 0.17677669529663687f;   // 1/sqrt(32)

        const float* qrow = Q + ((size_t)(b * 64 + n)) * DIMC + h * HDIM + q * 8;
        float4 v0 = *(const float4*)qrow;
        float4 v1 = *(const float4*)(qrow + 4);
        Qs[n][q*8+0] = v0.x * scale;  Qs[n][q*8+1] = v0.y * scale;
        Qs[n][q*8+2] = v0.z * scale;  Qs[n][q*8+3] = v0.w * scale;
        Qs[n][q*8+4] = v1.x * scale;  Qs[n][q*8+5] = v1.y * scale;
        Qs[n][q*8+6] = v1.z * scale;  Qs[n][q*8+7] = v1.w * scale;

        const float* krow = KV + ((size_t)(b * 64 + n)) * (2 * DIMC) + h * HDIM + q * 8;
        v0 = *(const float4*)krow;
        v1 = *(const float4*)(krow + 4);
        Ks[n][q*8+0] = v0.x;  Ks[n][q*8+1] = v0.y;
        Ks[n][q*8+2] = v0.z;  Ks[n][q*8+3] = v0.w;
        Ks[n][q*8+4] = v1.x;  Ks[n][q*8+5] = v1.y;
        Ks[n][q*8+6] = v1.z;  Ks[n][q*8+7] = v1.w;

        const float* vrow = krow + DIMC;
        v0 = *(const float4*)vrow;
        v1 = *(const float4*)(vrow + 4);
        Vt[q*8+0][n] = v0.x;  Vt[q*8+1][n] = v0.y;
        Vt[q*8+2][n] = v0.z;  Vt[q*8+3][n] = v0.w;
        Vt[q*8+4][n] = v1.x;  Vt[q*8+5][n] = v1.y;
        Vt[q*8+6][n] = v1.z;  Vt[q*8+7][n] = v1.w;
    }
    {
        const float* mbase = mask + (size_t)w * 4096;
        for (int i = tid; i < 4096; i += 256)
            Add[i] = rpb[rpi[i] * HEADS + h] + mbase[i];
    }
    __syncthreads();

    const int warp = tid >> 5;
    const int lane = tid & 31;

    unsigned long long k0[16], k1[16];
    {
        const ulonglong2* p0 = (const ulonglong2*)&Ks[lane][0];
        const ulonglong2* p1 = (const ulonglong2*)&Ks[lane + 32][0];
#pragma unroll
        for (int t = 0; t < 8; t++) {
            ulonglong2 a = p0[t]; k0[2*t] = a.x; k0[2*t+1] = a.y;
            ulonglong2 c = p1[t]; k1[2*t] = c.x; k1[2*t+1] = c.y;
        }
    }

#pragma unroll 1
    for (int r = 0; r < 8; r++) {
        const int n = warp * 8 + r;

        const ulonglong2* qp = (const ulonglong2*)&Qs[n][0];
        unsigned long long a0 = 0ull, a1 = 0ull;
#pragma unroll
        for (int t = 0; t < 8; t++) {
            ulonglong2 q2 = qp[t];
            a0 = ffma2(k0[2*t],   q2.x, a0);
            a0 = ffma2(k0[2*t+1], q2.y, a0);
            a1 = ffma2(k1[2*t],   q2.x, a1);
            a1 = ffma2(k1[2*t+1], q2.y, a1);
        }
        float s0 = u64lo(a0) + u64hi(a0) + Add[n * 64 + lane];
        float s1 = u64lo(a1) + u64hi(a1) + Add[n * 64 + lane + 32];

        float mx = fmaxf(s0, s1);
#pragma unroll
        for (int o = 16; o; o >>= 1) mx = fmaxf(mx, __shfl_xor_sync(0xffffffffu, mx, o));
        float e0 = __expf(s0 - mx);
        float e1 = __expf(s1 - mx);
        float sum = e0 + e1;
#pragma unroll
        for (int o = 16; o; o >>= 1) sum += __shfl_xor_sync(0xffffffffu, sum, o);
        float inv = 1.0f / sum;
        Ps[warp][lane]      = e0 * inv;
        Ps[warp][lane + 32] = e1 * inv;
        __syncwarp();

        const ulonglong2* pp = (const ulonglong2*)&Ps[warp][0];
        const ulonglong2* vp = (const ulonglong2*)&Vt[lane][0];
        unsigned long long oa = 0ull;
#pragma unroll
        for (int t = 0; t < 16; t++) {
            ulonglong2 P = pp[t];
            ulonglong2 V = vp[t];
            oa = ffma2(V.x, P.x, oa);
            oa = ffma2(V.y, P.y, oa);
        }
        O[((size_t)(b * 64 + n)) * DIMC + h * HDIM + lane] = u64lo(oa) + u64hi(oa);
        __syncwarp();
    }
}

// ---------------------------------------------------------------------------
// launcher
// ---------------------------------------------------------------------------
extern "C" void kernel_launch(void* const* d_in, const int* in_sizes, int n_in,
                              void* d_out, int out_size)
{
    const float* x    = (const float*)d_in[0];
    const float* px   = (const float*)d_in[1];
    const float* mask = (const float*)d_in[2];
    const int*   rpi  = (const int*)  d_in[3];
    const float* rpb  = (const float*)d_in[4];
    const float* wq   = (const float*)d_in[5];
    const float* bq   = (const float*)d_in[6];
    const float* wkv  = (const float*)d_in[7];
    const float* bkv  = (const float*)d_in[8];
    const float* wp   = (const float*)d_in[9];
    const float* bp   = (const float*)d_in[10];
    float* out = (float*)d_out;

    float *qbuf, *kvbuf, *obuf;
    cudaGetSymbolAddress((void**)&qbuf,  g_Q);
    cudaGetSymbolAddress((void**)&kvbuf, g_KV);
    cudaGetSymbolAddress((void**)&obuf,  g_O);

    cudaFuncSetAttribute(gemm_hmma_kernel,
                         cudaFuncAttributeMaxDynamicSharedMemorySize, SM_TOTAL);

    // Q = x @ wq^T + bq
    gemm_hmma_kernel<<<152, 256, SM_TOTAL>>>(x, wq, bq, qbuf, DIMC);
    // K half of KV
    gemm_hmma_kernel<<<152, 256, SM_TOTAL>>>(px, wkv, bkv, kvbuf, 2 * DIMC);
    // V half of KV
    gemm_hmma_kernel<<<152, 256, SM_TOTAL>>>(px, wkv + DIMC * DIMC, bkv + DIMC,
                                             kvbuf + DIMC, 2 * DIMC);
    // attention
    attn_kernel<<<dim3(HEADS, BWIN), 256>>>(qbuf, kvbuf, mask, rpi, rpb, obuf);
    // out = attn @ wp^T + bp
    gemm_hmma_kernel<<<152, 256, SM_TOTAL>>>(obuf, wp, bp, out, DIMC);
}

// round 4
// speedup vs baseline: 1.8777x; 1.4710x over previous
#include <cuda_runtime.h>
#include <cuda_bf16.h>
#include <cstdint>

// ---------------------------------------------------------------------------
// Problem constants
// ---------------------------------------------------------------------------
#define NW        192
#define BWIN      1536
#define NTOK      64
#define DIMC      192
#define HEADS     6
#define HDIM      32
#define M_TOT     (BWIN * NTOK)     // 98304
#define MTILES    (M_TOT / 128)     // 768

// scratch
__device__ float g_Q  [M_TOT * DIMC];
__device__ float g_KV [M_TOT * 2 * DIMC];
__device__ float g_O  [M_TOT * DIMC];
__device__ float g_ADD[NW * HEADS * 4096];   // combined rpb+mask table, 18.9MB

// ---------------------------------------------------------------------------
// helpers
// ---------------------------------------------------------------------------
// fp32 -> bf16 hi/lo split of 4 consecutive values -> two packed uint2
__device__ __forceinline__ void split4(float4 v, uint2& hi, uint2& lo) {
    __nv_bfloat16 h0 = __float2bfloat16_rn(v.x);
    __nv_bfloat16 h1 = __float2bfloat16_rn(v.y);
    __nv_bfloat16 h2 = __float2bfloat16_rn(v.z);
    __nv_bfloat16 h3 = __float2bfloat16_rn(v.w);
    __nv_bfloat16 l0 = __float2bfloat16_rn(v.x - __bfloat162float(h0));
    __nv_bfloat16 l1 = __float2bfloat16_rn(v.y - __bfloat162float(h1));
    __nv_bfloat16 l2 = __float2bfloat16_rn(v.z - __bfloat162float(h2));
    __nv_bfloat16 l3 = __float2bfloat16_rn(v.w - __bfloat162float(h3));
    union { __nv_bfloat162 b; uint32_t u; } c0, c1, c2, c3;
    c0.b = __halves2bfloat162(h0, h1);  c1.b = __halves2bfloat162(h2, h3);
    c2.b = __halves2bfloat162(l0, l1);  c3.b = __halves2bfloat162(l2, l3);
    hi.x = c0.u; hi.y = c1.u;
    lo.x = c2.u; lo.y = c3.u;
}
// fp32 pair -> packed bf16x2 hi + lo residual
__device__ __forceinline__ void split2(float p0, float p1, uint32_t& hi, uint32_t& lo) {
    __nv_bfloat16 h0 = __float2bfloat16_rn(p0);
    __nv_bfloat16 h1 = __float2bfloat16_rn(p1);
    __nv_bfloat16 l0 = __float2bfloat16_rn(p0 - __bfloat162float(h0));
    __nv_bfloat16 l1 = __float2bfloat16_rn(p1 - __bfloat162float(h1));
    union { __nv_bfloat162 b; uint32_t u; } a, b;
    a.b = __halves2bfloat162(h0, h1);
    b.b = __halves2bfloat162(l0, l1);
    hi = a.u; lo = b.u;
}

// mma.sync m16n8k16 row.col f32 += bf16*bf16
__device__ __forceinline__ void hmma(float* d, const uint32_t* a,
                                     uint32_t b0, uint32_t b1) {
    asm volatile(
        "mma.sync.aligned.m16n8k16.row.col.f32.bf16.bf16.f32 "
        "{%0,%1,%2,%3}, {%4,%5,%6,%7}, {%8,%9}, {%0,%1,%2,%3};"
        : "+f"(d[0]), "+f"(d[1]), "+f"(d[2]), "+f"(d[3])
        : "r"(a[0]), "r"(a[1]), "r"(a[2]), "r"(a[3]), "r"(b0), "r"(b1));
}

// ---------------------------------------------------------------------------
// bias table precompute: T[(w*6+h)*4096 + i] = rpb[rpi[i]*6+h] + mask[w*4096+i]
// ---------------------------------------------------------------------------
__global__ void __launch_bounds__(256)
addtable_kernel(const float* __restrict__ mask, const int* __restrict__ rpi,
                const float* __restrict__ rpb, float* __restrict__ T)
{
    int idx = blockIdx.x * 256 + threadIdx.x;
    int i   = idx & 4095;
    int wh  = idx >> 12;
    int hd  = wh % HEADS;
    int w   = wh / HEADS;
    T[idx] = rpb[rpi[i] * HEADS + hd] + mask[w * 4096 + i];
}

// ---------------------------------------------------------------------------
// HMMA GEMM: Y[M,192] = A[M,192] @ W[192,192]^T + bias  (bf16x3 split)
// persistent CTAs, register-prefetch double buffering of A chunks
// ---------------------------------------------------------------------------
#define WSTRIDE 200
#define ASTRIDE 104

#define SM_WHI   0
#define SM_WLO   (SM_WHI + 192 * WSTRIDE * 2)
#define SM_AHI   (SM_WLO + 192 * WSTRIDE * 2)
#define SM_ALO   (SM_AHI + 128 * ASTRIDE * 2)
#define SM_BIAS  (SM_ALO + 128 * ASTRIDE * 2)
#define SM_TOTAL (SM_BIAS + 192 * 4)

__global__ void __launch_bounds__(256, 1)
gemm_hmma_kernel(const float* __restrict__ A, const float* __restrict__ W,
                 const float* __restrict__ bias, float* __restrict__ Y, int ldY)
{
    extern __shared__ char smem[];
    __nv_bfloat16* whi = (__nv_bfloat16*)(smem + SM_WHI);
    __nv_bfloat16* wlo = (__nv_bfloat16*)(smem + SM_WLO);
    __nv_bfloat16* ahi = (__nv_bfloat16*)(smem + SM_AHI);
    __nv_bfloat16* alo = (__nv_bfloat16*)(smem + SM_ALO);
    float*         bss = (float*)       (smem + SM_BIAS);

    const int tid  = threadIdx.x;
    const int lane = tid & 31;
    const int warp = tid >> 5;
    const int wm   = warp >> 1;
    const int wn   = warp & 1;

    for (int i = tid; i < 192 * 48; i += 256) {
        int row = i / 48;
        int k4  = (i % 48) * 4;
        float4 v = *(const float4*)(W + (size_t)row * DIMC + k4);
        uint2 hi, lo; split4(v, hi, lo);
        *(uint2*)(whi + row * WSTRIDE + k4) = hi;
        *(uint2*)(wlo + row * WSTRIDE + k4) = lo;
    }
    if (tid < DIMC) bss[tid] = bias[tid];
    __syncthreads();

    const int fr = lane >> 2;
    const int fc = (lane & 3) * 2;
    const int prow = tid / 24 * 0;   // (unused placeholder removed below)

    float4 pf[12];
    int tile = blockIdx.x;
    if (tile < MTILES) {
#pragma unroll
        for (int j = 0; j < 12; j++) {
            int i = tid + j * 256;
            int row = i / 24, c4 = (i % 24) * 4;
            pf[j] = *(const float4*)(A + (size_t)(tile * 128 + row) * DIMC + c4);
        }
    }

    for (; tile < MTILES; tile += gridDim.x) {
        float acc[2][12][4];
#pragma unroll
        for (int mi = 0; mi < 2; mi++)
#pragma unroll
            for (int nt = 0; nt < 12; nt++)
#pragma unroll
                for (int j = 0; j < 4; j++) acc[mi][nt][j] = 0.f;

#pragma unroll 1
        for (int c = 0; c < 2; c++) {
            __syncthreads();
            // store prefetched chunk into smem (convert to bf16 hi/lo)
#pragma unroll
            for (int j = 0; j < 12; j++) {
                int i = tid + j * 256;
                int row = i / 24, c4 = (i % 24) * 4;
                uint2 hi, lo; split4(pf[j], hi, lo);
                *(uint2*)(ahi + row * ASTRIDE + c4) = hi;
                *(uint2*)(alo + row * ASTRIDE + c4) = lo;
            }
            __syncthreads();

            // prefetch next chunk (overlaps with MMAs below)
            int nc = c + 1, ntile = tile;
            if (nc == 2) { nc = 0; ntile = tile + gridDim.x; }
            if (ntile < MTILES) {
#pragma unroll
                for (int j = 0; j < 12; j++) {
                    int i = tid + j * 256;
                    int row = i / 24, c4 = (i % 24) * 4;
                    pf[j] = *(const float4*)(A + (size_t)(ntile * 128 + row) * DIMC
                                               + nc * 96 + c4);
                }
            }

#pragma unroll
            for (int ks = 0; ks < 6; ks++) {
                const int kk = ks * 16;
                uint32_t fa_hi[2][4], fa_lo[2][4];
#pragma unroll
                for (int mi = 0; mi < 2; mi++) {
                    int r0 = wm * 32 + mi * 16 + fr;
                    const char* bh = (const char*)ahi;
                    const char* bl = (const char*)alo;
                    uint32_t o00 = (uint32_t)((r0     * ASTRIDE + kk + fc    ) * 2);
                    uint32_t o10 = (uint32_t)(((r0+8) * ASTRIDE + kk + fc    ) * 2);
                    uint32_t o01 = (uint32_t)((r0     * ASTRIDE + kk + fc + 8) * 2);
                    uint32_t o11 = (uint32_t)(((r0+8) * ASTRIDE + kk + fc + 8) * 2);
                    fa_hi[mi][0] = *(const uint32_t*)(bh + o00);
                    fa_hi[mi][1] = *(const uint32_t*)(bh + o10);
                    fa_hi[mi][2] = *(const uint32_t*)(bh + o01);
                    fa_hi[mi][3] = *(const uint32_t*)(bh + o11);
                    fa_lo[mi][0] = *(const uint32_t*)(bl + o00);
                    fa_lo[mi][1] = *(const uint32_t*)(bl + o10);
                    fa_lo[mi][2] = *(const uint32_t*)(bl + o01);
                    fa_lo[mi][3] = *(const uint32_t*)(bl + o11);
                }
                const int kg = c * 96 + kk + fc;
#pragma unroll
                for (int nt = 0; nt < 12; nt++) {
                    int nrow = wn * 96 + nt * 8 + fr;
                    uint32_t ob0 = (uint32_t)((nrow * WSTRIDE + kg    ) * 2);
                    uint32_t ob1 = (uint32_t)((nrow * WSTRIDE + kg + 8) * 2);
                    uint32_t bh0 = *(const uint32_t*)((const char*)whi + ob0);
                    uint32_t bh1 = *(const uint32_t*)((const char*)whi + ob1);
                    uint32_t bl0 = *(const uint32_t*)((const char*)wlo + ob0);
                    uint32_t bl1 = *(const uint32_t*)((const char*)wlo + ob1);
#pragma unroll
                    for (int mi = 0; mi < 2; mi++) {
                        hmma(acc[mi][nt], fa_hi[mi], bh0, bh1);
                        hmma(acc[mi][nt], fa_lo[mi], bh0, bh1);
                        hmma(acc[mi][nt], fa_hi[mi], bl0, bl1);
                    }
                }
            }
        }

#pragma unroll
        for (int mi = 0; mi < 2; mi++) {
            int row = tile * 128 + wm * 32 + mi * 16 + fr;
#pragma unroll
            for (int nt = 0; nt < 12; nt++) {
                int col = wn * 96 + nt * 8 + fc;
                float2 bv = *(const float2*)&bss[col];
                float2 r0, r1;
                r0.x = acc[mi][nt][0] + bv.x;  r0.y = acc[mi][nt][1] + bv.y;
                r1.x = acc[mi][nt][2] + bv.x;  r1.y = acc[mi][nt][3] + bv.y;
                *(float2*)&Y[(size_t)row       * ldY + col] = r0;
                *(float2*)&Y[(size_t)(row + 8) * ldY + col] = r1;
            }
        }
    }
}

// ---------------------------------------------------------------------------
// HMMA fused windowed attention: one block per window, all 6 heads.
// S = QK^T (bf16x3 MMA) + ADD table -> fragment softmax -> O = PV (bf16x3 MMA)
// ---------------------------------------------------------------------------
#define QSTR 200     // bf16 stride for Q/K tiles (64 x 192)
#define VSTR 72      // bf16 stride for Vt (192 x 64)

#define AT_QH 0
#define AT_QL (AT_QH + 64 * QSTR * 2)
#define AT_KH (AT_QL + 64 * QSTR * 2)
#define AT_KL (AT_KH + 64 * QSTR * 2)
#define AT_VH (AT_KL + 64 * QSTR * 2)
#define AT_VL (AT_VH + 192 * VSTR * 2)
#define AT_TOTAL (AT_VL + 192 * VSTR * 2)    // 157696 B

__global__ void __launch_bounds__(384, 1)
attn_hmma_kernel(const float* __restrict__ Q, const float* __restrict__ KV,
                 const float* __restrict__ ADDT, float* __restrict__ O)
{
    extern __shared__ char smem[];
    __nv_bfloat16* qh = (__nv_bfloat16*)(smem + AT_QH);
    __nv_bfloat16* ql = (__nv_bfloat16*)(smem + AT_QL);
    __nv_bfloat16* kh = (__nv_bfloat16*)(smem + AT_KH);
    __nv_bfloat16* kl = (__nv_bfloat16*)(smem + AT_KL);
    __nv_bfloat16* vh = (__nv_bfloat16*)(smem + AT_VH);
    __nv_bfloat16* vl = (__nv_bfloat16*)(smem + AT_VL);

    const int b   = blockIdx.x;
    const int w   = b % NW;
    const int tid = threadIdx.x;
    const float scale = 0.17677669529663687f;   // 1/sqrt(32)

    // ---- convert Q (scaled), K, V(transposed) to bf16 hi/lo in smem ----
    for (int i = tid; i < 64 * 48; i += 384) {
        int row = i / 48, c4 = (i % 48) * 4;
        float4 v = *(const float4*)(Q + (size_t)(b * 64 + row) * DIMC + c4);
        v.x *= scale; v.y *= scale; v.z *= scale; v.w *= scale;
        uint2 hi, lo; split4(v, hi, lo);
        *(uint2*)(qh + row * QSTR + c4) = hi;
        *(uint2*)(ql + row * QSTR + c4) = lo;
    }
    for (int i = tid; i < 64 * 48; i += 384) {
        int row = i / 48, c4 = (i % 48) * 4;
        const float* base = KV + (size_t)(b * 64 + row) * (2 * DIMC);
        float4 v = *(const float4*)(base + c4);
        uint2 hi, lo; split4(v, hi, lo);
        *(uint2*)(kh + row * QSTR + c4) = hi;
        *(uint2*)(kl + row * QSTR + c4) = lo;

        float4 vv = *(const float4*)(base + DIMC + c4);
        float vals[4] = {vv.x, vv.y, vv.z, vv.w};
#pragma unroll
        for (int j = 0; j < 4; j++) {
            __nv_bfloat16 h = __float2bfloat16_rn(vals[j]);
            __nv_bfloat16 l = __float2bfloat16_rn(vals[j] - __bfloat162float(h));
            vh[(c4 + j) * VSTR + row] = h;
            vl[(c4 + j) * VSTR + row] = l;
        }
    }
    __syncthreads();

    const int warp = tid >> 5;
    const int lane = tid & 31;
    const int fr   = lane >> 2;
    const int fc   = (lane & 3) * 2;

#pragma unroll 1
    for (int uu = 0; uu < 2; uu++) {
        const int u  = warp * 2 + uu;    // 0..23
        const int hd = u >> 2;           // head 0..5
        const int mt = u & 3;            // m-tile 0..3
        const int r0 = mt * 16 + fr;
        const int kb = hd * 32;

        // ---- S = Q K^T ----
        float acc[8][4];
#pragma unroll
        for (int nt = 0; nt < 8; nt++)
#pragma unroll
            for (int j = 0; j < 4; j++) acc[nt][j] = 0.f;

#pragma unroll
        for (int ks = 0; ks < 2; ks++) {
            const int kk = kb + ks * 16;
            uint32_t ah[4], al[4];
            ah[0] = *(const uint32_t*)(qh + (r0    ) * QSTR + kk + fc);
            ah[1] = *(const uint32_t*)(qh + (r0 + 8) * QSTR + kk + fc);
            ah[2] = *(const uint32_t*)(qh + (r0    ) * QSTR + kk + 8 + fc);
            ah[3] = *(const uint32_t*)(qh + (r0 + 8) * QSTR + kk + 8 + fc);
            al[0] = *(const uint32_t*)(ql + (r0    ) * QSTR + kk + fc);
            al[1] = *(const uint32_t*)(ql + (r0 + 8) * QSTR + kk + fc);
            al[2] = *(const uint32_t*)(ql + (r0    ) * QSTR + kk + 8 + fc);
            al[3] = *(const uint32_t*)(ql + (r0 + 8) * QSTR + kk + 8 + fc);
#pragma unroll
            for (int nt = 0; nt < 8; nt++) {
                int nr = nt * 8 + fr;
                uint32_t bh0 = *(const uint32_t*)(kh + nr * QSTR + kk + fc);
                uint32_t bh1 = *(const uint32_t*)(kh + nr * QSTR + kk + 8 + fc);
                uint32_t bl0 = *(const uint32_t*)(kl + nr * QSTR + kk + fc);
                uint32_t bl1 = *(const uint32_t*)(kl + nr * QSTR + kk + 8 + fc);
                hmma(acc[nt], ah, bh0, bh1);
                hmma(acc[nt], al, bh0, bh1);
                hmma(acc[nt], ah, bl0, bl1);
            }
        }

        // ---- add combined bias+mask table ----
        const float* T = ADDT + ((size_t)(w * HEADS + hd)) * 4096;
#pragma unroll
        for (int nt = 0; nt < 8; nt++) {
            int cc = nt * 8 + fc;
            float2 t0 = *(const float2*)(T + (r0    ) * 64 + cc);
            float2 t1 = *(const float2*)(T + (r0 + 8) * 64 + cc);
            acc[nt][0] += t0.x;  acc[nt][1] += t0.y;
            acc[nt][2] += t1.x;  acc[nt][3] += t1.y;
        }

        // ---- fragment softmax (rows r0 and r0+8, reduce across quad) ----
        float m0 = -1e30f, m1 = -1e30f;
#pragma unroll
        for (int nt = 0; nt < 8; nt++) {
            m0 = fmaxf(m0, fmaxf(acc[nt][0], acc[nt][1]));
            m1 = fmaxf(m1, fmaxf(acc[nt][2], acc[nt][3]));
        }
        m0 = fmaxf(m0, __shfl_xor_sync(0xffffffffu, m0, 1));
        m0 = fmaxf(m0, __shfl_xor_sync(0xffffffffu, m0, 2));
        m1 = fmaxf(m1, __shfl_xor_sync(0xffffffffu, m1, 1));
        m1 = fmaxf(m1, __shfl_xor_sync(0xffffffffu, m1, 2));

        float s0 = 0.f, s1 = 0.f;
#pragma unroll
        for (int nt = 0; nt < 8; nt++) {
            acc[nt][0] = __expf(acc[nt][0] - m0);  s0 += acc[nt][0];
            acc[nt][1] = __expf(acc[nt][1] - m0);  s0 += acc[nt][1];
            acc[nt][2] = __expf(acc[nt][2] - m1);  s1 += acc[nt][2];
            acc[nt][3] = __expf(acc[nt][3] - m1);  s1 += acc[nt][3];
        }
        s0 += __shfl_xor_sync(0xffffffffu, s0, 1);
        s0 += __shfl_xor_sync(0xffffffffu, s0, 2);
        s1 += __shfl_xor_sync(0xffffffffu, s1, 1);
        s1 += __shfl_xor_sync(0xffffffffu, s1, 2);
        float i0 = 1.f / s0, i1 = 1.f / s1;

        // ---- repack P into A-operand fragments (hi + lo residual) ----
        // a0=(r,k..k+1)  a1=(r+8,k..k+1)  a2=(r,k+8..k+9)  a3=(r+8,k+8..k+9)
        uint32_t phi[4][4], plo[4][4];
#pragma unroll
        for (int kt = 0; kt < 4; kt++) {
            split2(acc[2*kt  ][0] * i0, acc[2*kt  ][1] * i0, phi[kt][0], plo[kt][0]);
            split2(acc[2*kt  ][2] * i1, acc[2*kt  ][3] * i1, phi[kt][1], plo[kt][1]);
            split2(acc[2*kt+1][0] * i0, acc[2*kt+1][1] * i0, phi[kt][2], plo[kt][2]);
            split2(acc[2*kt+1][2] * i1, acc[2*kt+1][3] * i1, phi[kt][3], plo[kt][3]);
        }

        // ---- O = P V ----
        float oacc[4][4];
#pragma unroll
        for (int dt = 0; dt < 4; dt++)
#pragma unroll
            for (int j = 0; j < 4; j++) oacc[dt][j] = 0.f;

#pragma unroll
        for (int kt = 0; kt < 4; kt++) {
            const int tk = kt * 16 + fc;
#pragma unroll
            for (int dt = 0; dt < 4; dt++) {
                int dr = kb + dt * 8 + fr;
                uint32_t bh0 = *(const uint32_t*)(vh + dr * VSTR + tk);
                uint32_t bh1 = *(const uint32_t*)(vh + dr * VSTR + tk + 8);
                uint32_t bl0 = *(const uint32_t*)(vl + dr * VSTR + tk);
                uint32_t bl1 = *(const uint32_t*)(vl + dr * VSTR + tk + 8);
                hmma(oacc[dt], phi[kt], bh0, bh1);
                hmma(oacc[dt], plo[kt], bh0, bh1);
                hmma(oacc[dt], phi[kt], bl0, bl1);
            }
        }

        // ---- store O ----
#pragma unroll
        for (int dt = 0; dt < 4; dt++) {
            int col = kb + dt * 8 + fc;
            float2 o0, o1;
            o0.x = oacc[dt][0];  o0.y = oacc[dt][1];
            o1.x = oacc[dt][2];  o1.y = oacc[dt][3];
            *(float2*)(O + (size_t)(b * 64 + r0    ) * DIMC + col) = o0;
            *(float2*)(O + (size_t)(b * 64 + r0 + 8) * DIMC + col) = o1;
        }
    }
}

// ---------------------------------------------------------------------------
// launcher
// ---------------------------------------------------------------------------
extern "C" void kernel_launch(void* const* d_in, const int* in_sizes, int n_in,
                              void* d_out, int out_size)
{
    const float* x    = (const float*)d_in[0];
    const float* px   = (const float*)d_in[1];
    const float* mask = (const float*)d_in[2];
    const int*   rpi  = (const int*)  d_in[3];
    const float* rpb  = (const float*)d_in[4];
    const float* wq   = (const float*)d_in[5];
    const float* bq   = (const float*)d_in[6];
    const float* wkv  = (const float*)d_in[7];
    const float* bkv  = (const float*)d_in[8];
    const float* wp   = (const float*)d_in[9];
    const float* bp   = (const float*)d_in[10];
    float* out = (float*)d_out;

    float *qbuf, *kvbuf, *obuf, *addt;
    cudaGetSymbolAddress((void**)&qbuf,  g_Q);
    cudaGetSymbolAddress((void**)&kvbuf, g_KV);
    cudaGetSymbolAddress((void**)&obuf,  g_O);
    cudaGetSymbolAddress((void**)&addt,  g_ADD);

    cudaFuncSetAttribute(gemm_hmma_kernel,
                         cudaFuncAttributeMaxDynamicSharedMemorySize, SM_TOTAL);
    cudaFuncSetAttribute(attn_hmma_kernel,
                         cudaFuncAttributeMaxDynamicSharedMemorySize, AT_TOTAL);

    // bias+mask table (runs once per graph replay; cheap)
    addtable_kernel<<<NW * HEADS * 4096 / 256, 256>>>(mask, rpi, rpb, addt);

    // Q = x @ wq^T + bq
    gemm_hmma_kernel<<<152, 256, SM_TOTAL>>>(x, wq, bq, qbuf, DIMC);
    // K half of KV
    gemm_hmma_kernel<<<152, 256, SM_TOTAL>>>(px, wkv, bkv, kvbuf, 2 * DIMC);
    // V half of KV
    gemm_hmma_kernel<<<152, 256, SM_TOTAL>>>(px, wkv + DIMC * DIMC, bkv + DIMC,
                                             kvbuf + DIMC, 2 * DIMC);
    // attention (tensor-core)
    attn_hmma_kernel<<<BWIN, 384, AT_TOTAL>>>(qbuf, kvbuf, addt, obuf);
    // out = attn @ wp^T + bp
    gemm_hmma_kernel<<<152, 256, SM_TOTAL>>>(obuf, wp, bp, out, DIMC);
}

// round 5
// speedup vs baseline: 2.0635x; 1.0989x over previous
#include <cuda_runtime.h>
#include <cuda_bf16.h>
#include <cstdint>

// ---------------------------------------------------------------------------
// Problem constants
// ---------------------------------------------------------------------------
#define NW        192
#define BWIN      1536
#define NTOK      64
#define DIMC      192
#define HEADS     6
#define HDIM      32
#define M_TOT     (BWIN * NTOK)     // 98304
#define MTILES    (M_TOT / 128)     // 768

// scratch
__device__ float g_Q  [M_TOT * DIMC];
__device__ float g_KV [M_TOT * 2 * DIMC];
__device__ float g_O  [M_TOT * DIMC];
__device__ float g_ADD[NW * HEADS * 4096];

// ---------------------------------------------------------------------------
// helpers
// ---------------------------------------------------------------------------
__device__ __forceinline__ void split4(float4 v, uint2& hi, uint2& lo) {
    __nv_bfloat16 h0 = __float2bfloat16_rn(v.x);
    __nv_bfloat16 h1 = __float2bfloat16_rn(v.y);
    __nv_bfloat16 h2 = __float2bfloat16_rn(v.z);
    __nv_bfloat16 h3 = __float2bfloat16_rn(v.w);
    __nv_bfloat16 l0 = __float2bfloat16_rn(v.x - __bfloat162float(h0));
    __nv_bfloat16 l1 = __float2bfloat16_rn(v.y - __bfloat162float(h1));
    __nv_bfloat16 l2 = __float2bfloat16_rn(v.z - __bfloat162float(h2));
    __nv_bfloat16 l3 = __float2bfloat16_rn(v.w - __bfloat162float(h3));
    union { __nv_bfloat162 b; uint32_t u; } c0, c1, c2, c3;
    c0.b = __halves2bfloat162(h0, h1);  c1.b = __halves2bfloat162(h2, h3);
    c2.b = __halves2bfloat162(l0, l1);  c3.b = __halves2bfloat162(l2, l3);
    hi.x = c0.u; hi.y = c1.u;
    lo.x = c2.u; lo.y = c3.u;
}
__device__ __forceinline__ void split2(float p0, float p1, uint32_t& hi, uint32_t& lo) {
    __nv_bfloat16 h0 = __float2bfloat16_rn(p0);
    __nv_bfloat16 h1 = __float2bfloat16_rn(p1);
    __nv_bfloat16 l0 = __float2bfloat16_rn(p0 - __bfloat162float(h0));
    __nv_bfloat16 l1 = __float2bfloat16_rn(p1 - __bfloat162float(h1));
    union { __nv_bfloat162 b; uint32_t u; } a, b;
    a.b = __halves2bfloat162(h0, h1);
    b.b = __halves2bfloat162(l0, l1);
    hi = a.u; lo = b.u;
}
__device__ __forceinline__ void hmma(float* d, const uint32_t* a,
                                     uint32_t b0, uint32_t b1) {
    asm volatile(
        "mma.sync.aligned.m16n8k16.row.col.f32.bf16.bf16.f32 "
        "{%0,%1,%2,%3}, {%4,%5,%6,%7}, {%8,%9}, {%0,%1,%2,%3};"
        : "+f"(d[0]), "+f"(d[1]), "+f"(d[2]), "+f"(d[3])
        : "r"(a[0]), "r"(a[1]), "r"(a[2]), "r"(a[3]), "r"(b0), "r"(b1));
}

// ---------------------------------------------------------------------------
// bias table: T[(w*6+h)*4096 + i] = rpb[rpi[i]*6+h] + mask[w*4096+i]
// ---------------------------------------------------------------------------
__global__ void __launch_bounds__(256)
addtable_kernel(const float* __restrict__ mask, const int* __restrict__ rpi,
                const float* __restrict__ rpb, float* __restrict__ T)
{
    int idx = blockIdx.x * 256 + threadIdx.x;
    int i   = idx & 4095;
    int wh  = idx >> 12;
    int hd  = wh % HEADS;
    int w   = wh / HEADS;
    T[idx] = rpb[rpi[i] * HEADS + hd] + mask[w * 4096 + i];
}

// ---------------------------------------------------------------------------
// HMMA GEMM: Y[M,192] = A[M,192] @ W[192,192]^T + bias  (bf16x3 split)
// 512 threads (16 warps, 4Mx4N), warp tile 32x48, persistent CTAs,
// register-prefetch double buffering.
// ---------------------------------------------------------------------------
#define WSTRIDE 200
#define ASTRIDE 104

#define SM_WHI   0
#define SM_WLO   (SM_WHI + 192 * WSTRIDE * 2)
#define SM_AHI   (SM_WLO + 192 * WSTRIDE * 2)
#define SM_ALO   (SM_AHI + 128 * ASTRIDE * 2)
#define SM_BIAS  (SM_ALO + 128 * ASTRIDE * 2)
#define SM_TOTAL (SM_BIAS + 192 * 4)

__global__ void __launch_bounds__(512, 1)
gemm_hmma_kernel(const float* __restrict__ A, const float* __restrict__ W,
                 const float* __restrict__ bias, float* __restrict__ Y, int ldY)
{
    extern __shared__ char smem[];
    __nv_bfloat16* whi = (__nv_bfloat16*)(smem + SM_WHI);
    __nv_bfloat16* wlo = (__nv_bfloat16*)(smem + SM_WLO);
    __nv_bfloat16* ahi = (__nv_bfloat16*)(smem + SM_AHI);
    __nv_bfloat16* alo = (__nv_bfloat16*)(smem + SM_ALO);
    float*         bss = (float*)       (smem + SM_BIAS);

    const int tid  = threadIdx.x;
    const int lane = tid & 31;
    const int warp = tid >> 5;
    const int wm   = warp & 3;           // 4 M-tiles of 32 rows
    const int wn   = warp >> 2;          // 4 N-groups of 48 cols

    for (int i = tid; i < 192 * 48; i += 512) {
        int row = i / 48;
        int k4  = (i % 48) * 4;
        float4 v = *(const float4*)(W + (size_t)row * DIMC + k4);
        uint2 hi, lo; split4(v, hi, lo);
        *(uint2*)(whi + row * WSTRIDE + k4) = hi;
        *(uint2*)(wlo + row * WSTRIDE + k4) = lo;
    }
    if (tid < DIMC) bss[tid] = bias[tid];
    __syncthreads();

    const int fr = lane >> 2;
    const int fc = (lane & 3) * 2;

    float4 pf[6];
    int tile = blockIdx.x;
    if (tile < MTILES) {
#pragma unroll
        for (int j = 0; j < 6; j++) {
            int i = tid + j * 512;
            int row = i / 24, c4 = (i % 24) * 4;
            pf[j] = *(const float4*)(A + (size_t)(tile * 128 + row) * DIMC + c4);
        }
    }

    for (; tile < MTILES; tile += gridDim.x) {
        float acc[2][6][4];
#pragma unroll
        for (int mi = 0; mi < 2; mi++)
#pragma unroll
            for (int nt = 0; nt < 6; nt++)
#pragma unroll
                for (int j = 0; j < 4; j++) acc[mi][nt][j] = 0.f;

#pragma unroll 1
        for (int c = 0; c < 2; c++) {
            __syncthreads();
#pragma unroll
            for (int j = 0; j < 6; j++) {
                int i = tid + j * 512;
                int row = i / 24, c4 = (i % 24) * 4;
                uint2 hi, lo; split4(pf[j], hi, lo);
                *(uint2*)(ahi + row * ASTRIDE + c4) = hi;
                *(uint2*)(alo + row * ASTRIDE + c4) = lo;
            }
            __syncthreads();

            int nc = c + 1, ntile = tile;
            if (nc == 2) { nc = 0; ntile = tile + gridDim.x; }
            if (ntile < MTILES) {
#pragma unroll
                for (int j = 0; j < 6; j++) {
                    int i = tid + j * 512;
                    int row = i / 24, c4 = (i % 24) * 4;
                    pf[j] = *(const float4*)(A + (size_t)(ntile * 128 + row) * DIMC
                                               + nc * 96 + c4);
                }
            }

#pragma unroll
            for (int ks = 0; ks < 6; ks++) {
                const int kk = ks * 16;
                uint32_t fa_hi[2][4], fa_lo[2][4];
#pragma unroll
                for (int mi = 0; mi < 2; mi++) {
                    int r0 = wm * 32 + mi * 16 + fr;
                    const char* bh = (const char*)ahi;
                    const char* bl = (const char*)alo;
                    uint32_t o00 = (uint32_t)((r0     * ASTRIDE + kk + fc    ) * 2);
                    uint32_t o10 = (uint32_t)(((r0+8) * ASTRIDE + kk + fc    ) * 2);
                    uint32_t o01 = (uint32_t)((r0     * ASTRIDE + kk + fc + 8) * 2);
                    uint32_t o11 = (uint32_t)(((r0+8) * ASTRIDE + kk + fc + 8) * 2);
                    fa_hi[mi][0] = *(const uint32_t*)(bh + o00);
                    fa_hi[mi][1] = *(const uint32_t*)(bh + o10);
                    fa_hi[mi][2] = *(const uint32_t*)(bh + o01);
                    fa_hi[mi][3] = *(const uint32_t*)(bh + o11);
                    fa_lo[mi][0] = *(const uint32_t*)(bl + o00);
                    fa_lo[mi][1] = *(const uint32_t*)(bl + o10);
                    fa_lo[mi][2] = *(const uint32_t*)(bl + o01);
                    fa_lo[mi][3] = *(const uint32_t*)(bl + o11);
                }
                const int kg = c * 96 + kk + fc;
#pragma unroll
                for (int nt = 0; nt < 6; nt++) {
                    int nrow = wn * 48 + nt * 8 + fr;
                    uint32_t ob0 = (uint32_t)((nrow * WSTRIDE + kg    ) * 2);
                    uint32_t ob1 = (uint32_t)((nrow * WSTRIDE + kg + 8) * 2);
                    uint32_t bh0 = *(const uint32_t*)((const char*)whi + ob0);
                    uint32_t bh1 = *(const uint32_t*)((const char*)whi + ob1);
                    uint32_t bl0 = *(const uint32_t*)((const char*)wlo + ob0);
                    uint32_t bl1 = *(const uint32_t*)((const char*)wlo + ob1);
#pragma unroll
                    for (int mi = 0; mi < 2; mi++) {
                        hmma(acc[mi][nt], fa_hi[mi], bh0, bh1);
                        hmma(acc[mi][nt], fa_lo[mi], bh0, bh1);
                        hmma(acc[mi][nt], fa_hi[mi], bl0, bl1);
                    }
                }
            }
        }

#pragma unroll
        for (int mi = 0; mi < 2; mi++) {
            int row = tile * 128 + wm * 32 + mi * 16 + fr;
#pragma unroll
            for (int nt = 0; nt < 6; nt++) {
                int col = wn * 48 + nt * 8 + fc;
                float2 bv = *(const float2*)&bss[col];
                float2 r0, r1;
                r0.x = acc[mi][nt][0] + bv.x;  r0.y = acc[mi][nt][1] + bv.y;
                r1.x = acc[mi][nt][2] + bv.x;  r1.y = acc[mi][nt][3] + bv.y;
                *(float2*)&Y[(size_t)row       * ldY + col] = r0;
                *(float2*)&Y[(size_t)(row + 8) * ldY + col] = r1;
            }
        }
    }
}

// ---------------------------------------------------------------------------
// HMMA attention: one block per window, 768 threads, 1 (head,mtile) per warp.
// Q fragments loaded straight from gmem (no Q smem).
// ---------------------------------------------------------------------------
#define KSTR 200
#define VSTR 72

#define AT_KH 0
#define AT_KL (AT_KH + 64 * KSTR * 2)
#define AT_VH (AT_KL + 64 * KSTR * 2)
#define AT_VL (AT_VH + 192 * VSTR * 2)
#define AT_TOTAL (AT_VL + 192 * VSTR * 2)    // 106496 B

__global__ void __launch_bounds__(768, 1)
attn_hmma_kernel(const float* __restrict__ Q, const float* __restrict__ KV,
                 const float* __restrict__ ADDT, float* __restrict__ O)
{
    extern __shared__ char smem[];
    __nv_bfloat16* kh = (__nv_bfloat16*)(smem + AT_KH);
    __nv_bfloat16* kl = (__nv_bfloat16*)(smem + AT_KL);
    __nv_bfloat16* vh = (__nv_bfloat16*)(smem + AT_VH);
    __nv_bfloat16* vl = (__nv_bfloat16*)(smem + AT_VL);

    const int b   = blockIdx.x;
    const int w   = b % NW;
    const int tid = threadIdx.x;

    // ---- convert K, V(transposed) to bf16 hi/lo in smem ----
    for (int i = tid; i < 64 * 48; i += 768) {
        int row = i / 48, c4 = (i % 48) * 4;
        const float* base = KV + (size_t)(b * 64 + row) * (2 * DIMC);
        float4 v = *(const float4*)(base + c4);
        uint2 hi, lo; split4(v, hi, lo);
        *(uint2*)(kh + row * KSTR + c4) = hi;
        *(uint2*)(kl + row * KSTR + c4) = lo;

        float4 vv = *(const float4*)(base + DIMC + c4);
        float vals[4] = {vv.x, vv.y, vv.z, vv.w};
#pragma unroll
        for (int j = 0; j < 4; j++) {
            __nv_bfloat16 h = __float2bfloat16_rn(vals[j]);
            __nv_bfloat16 l = __float2bfloat16_rn(vals[j] - __bfloat162float(h));
            vh[(c4 + j) * VSTR + row] = h;
            vl[(c4 + j) * VSTR + row] = l;
        }
    }
    __syncthreads();

    const int warp = tid >> 5;      // 0..23
    const int lane = tid & 31;
    const int fr   = lane >> 2;
    const int fc   = (lane & 3) * 2;
    const int hd   = warp >> 2;     // head 0..5
    const int mt   = warp & 3;      // m-tile 0..3
    const int r0   = mt * 16 + fr;
    const int kb   = hd * 32;
    const float scale = 0.17677669529663687f;   // 1/sqrt(32)

    // ---- S = Q K^T ----
    float acc[8][4];
#pragma unroll
    for (int nt = 0; nt < 8; nt++)
#pragma unroll
        for (int j = 0; j < 4; j++) acc[nt][j] = 0.f;

#pragma unroll
    for (int ks = 0; ks < 2; ks++) {
        const int kk = kb + ks * 16;
        // Q fragment direct from gmem (scaled, bf16 hi/lo split)
        const float* q0 = Q + (size_t)(b * 64 + r0) * DIMC + kk + fc;
        float2 f00 = *(const float2*)(q0);
        float2 f10 = *(const float2*)(q0 + 8 * DIMC);
        float2 f01 = *(const float2*)(q0 + 8);
        float2 f11 = *(const float2*)(q0 + 8 * DIMC + 8);
        uint32_t ah[4], al[4];
        split2(f00.x * scale, f00.y * scale, ah[0], al[0]);
        split2(f10.x * scale, f10.y * scale, ah[1], al[1]);
        split2(f01.x * scale, f01.y * scale, ah[2], al[2]);
        split2(f11.x * scale, f11.y * scale, ah[3], al[3]);
#pragma unroll
        for (int nt = 0; nt < 8; nt++) {
            int nr = nt * 8 + fr;
            uint32_t bh0 = *(const uint32_t*)(kh + nr * KSTR + kk + fc);
            uint32_t bh1 = *(const uint32_t*)(kh + nr * KSTR + kk + 8 + fc);
            uint32_t bl0 = *(const uint32_t*)(kl + nr * KSTR + kk + fc);
            uint32_t bl1 = *(const uint32_t*)(kl + nr * KSTR + kk + 8 + fc);
            hmma(acc[nt], ah, bh0, bh1);
            hmma(acc[nt], al, bh0, bh1);
            hmma(acc[nt], ah, bl0, bl1);
        }
    }

    // ---- add bias+mask table ----
    const float* T = ADDT + ((size_t)(w * HEADS + hd)) * 4096;
#pragma unroll
    for (int nt = 0; nt < 8; nt++) {
        int cc = nt * 8 + fc;
        float2 t0 = *(const float2*)(T + (r0    ) * 64 + cc);
        float2 t1 = *(const float2*)(T + (r0 + 8) * 64 + cc);
        acc[nt][0] += t0.x;  acc[nt][1] += t0.y;
        acc[nt][2] += t1.x;  acc[nt][3] += t1.y;
    }

    // ---- fragment softmax ----
    float m0 = -1e30f, m1 = -1e30f;
#pragma unroll
    for (int nt = 0; nt < 8; nt++) {
        m0 = fmaxf(m0, fmaxf(acc[nt][0], acc[nt][1]));
        m1 = fmaxf(m1, fmaxf(acc[nt][2], acc[nt][3]));
    }
    m0 = fmaxf(m0, __shfl_xor_sync(0xffffffffu, m0, 1));
    m0 = fmaxf(m0, __shfl_xor_sync(0xffffffffu, m0, 2));
    m1 = fmaxf(m1, __shfl_xor_sync(0xffffffffu, m1, 1));
    m1 = fmaxf(m1, __shfl_xor_sync(0xffffffffu, m1, 2));

    float s0 = 0.f, s1 = 0.f;
#pragma unroll
    for (int nt = 0; nt < 8; nt++) {
        acc[nt][0] = __expf(acc[nt][0] - m0);  s0 += acc[nt][0];
        acc[nt][1] = __expf(acc[nt][1] - m0);  s0 += acc[nt][1];
        acc[nt][2] = __expf(acc[nt][2] - m1);  s1 += acc[nt][2];
        acc[nt][3] = __expf(acc[nt][3] - m1);  s1 += acc[nt][3];
    }
    s0 += __shfl_xor_sync(0xffffffffu, s0, 1);
    s0 += __shfl_xor_sync(0xffffffffu, s0, 2);
    s1 += __shfl_xor_sync(0xffffffffu, s1, 1);
    s1 += __shfl_xor_sync(0xffffffffu, s1, 2);
    float i0 = 1.f / s0, i1 = 1.f / s1;

    // ---- repack P into A-operand fragments (hi + lo residual) ----
    uint32_t phi[4][4], plo[4][4];
#pragma unroll
    for (int kt = 0; kt < 4; kt++) {
        split2(acc[2*kt  ][0] * i0, acc[2*kt  ][1] * i0, phi[kt][0], plo[kt][0]);
        split2(acc[2*kt  ][2] * i1, acc[2*kt  ][3] * i1, phi[kt][1], plo[kt][1]);
        split2(acc[2*kt+1][0] * i0, acc[2*kt+1][1] * i0, phi[kt][2], plo[kt][2]);
        split2(acc[2*kt+1][2] * i1, acc[2*kt+1][3] * i1, phi[kt][3], plo[kt][3]);
    }

    // ---- O = P V ----
    float oacc[4][4];
#pragma unroll
    for (int dt = 0; dt < 4; dt++)
#pragma unroll
        for (int j = 0; j < 4; j++) oacc[dt][j] = 0.f;

#pragma unroll
    for (int kt = 0; kt < 4; kt++) {
        const int tk = kt * 16 + fc;
#pragma unroll
        for (int dt = 0; dt < 4; dt++) {
            int dr = kb + dt * 8 + fr;
            uint32_t bh0 = *(const uint32_t*)(vh + dr * VSTR + tk);
            uint32_t bh1 = *(const uint32_t*)(vh + dr * VSTR + tk + 8);
            uint32_t bl0 = *(const uint32_t*)(vl + dr * VSTR + tk);
            uint32_t bl1 = *(const uint32_t*)(vl + dr * VSTR + tk + 8);
            hmma(oacc[dt], phi[kt], bh0, bh1);
            hmma(oacc[dt], plo[kt], bh0, bh1);
            hmma(oacc[dt], phi[kt], bl0, bl1);
        }
    }

    // ---- store O ----
#pragma unroll
    for (int dt = 0; dt < 4; dt++) {
        int col = kb + dt * 8 + fc;
        float2 o0, o1;
        o0.x = oacc[dt][0];  o0.y = oacc[dt][1];
        o1.x = oacc[dt][2];  o1.y = oacc[dt][3];
        *(float2*)(O + (size_t)(b * 64 + r0    ) * DIMC + col) = o0;
        *(float2*)(O + (size_t)(b * 64 + r0 + 8) * DIMC + col) = o1;
    }
}

// ---------------------------------------------------------------------------
// launcher
// ---------------------------------------------------------------------------
extern "C" void kernel_launch(void* const* d_in, const int* in_sizes, int n_in,
                              void* d_out, int out_size)
{
    const float* x    = (const float*)d_in[0];
    const float* px   = (const float*)d_in[1];
    const float* mask = (const float*)d_in[2];
    const int*   rpi  = (const int*)  d_in[3];
    const float* rpb  = (const float*)d_in[4];
    const float* wq   = (const float*)d_in[5];
    const float* bq   = (const float*)d_in[6];
    const float* wkv  = (const float*)d_in[7];
    const float* bkv  = (const float*)d_in[8];
    const float* wp   = (const float*)d_in[9];
    const float* bp   = (const float*)d_in[10];
    float* out = (float*)d_out;

    float *qbuf, *kvbuf, *obuf, *addt;
    cudaGetSymbolAddress((void**)&qbuf,  g_Q);
    cudaGetSymbolAddress((void**)&kvbuf, g_KV);
    cudaGetSymbolAddress((void**)&obuf,  g_O);
    cudaGetSymbolAddress((void**)&addt,  g_ADD);

    cudaFuncSetAttribute(gemm_hmma_kernel,
                         cudaFuncAttributeMaxDynamicSharedMemorySize, SM_TOTAL);
    cudaFuncSetAttribute(attn_hmma_kernel,
                         cudaFuncAttributeMaxDynamicSharedMemorySize, AT_TOTAL);

    addtable_kernel<<<NW * HEADS * 4096 / 256, 256>>>(mask, rpi, rpb, addt);

    gemm_hmma_kernel<<<152, 512, SM_TOTAL>>>(x, wq, bq, qbuf, DIMC);
    gemm_hmma_kernel<<<152, 512, SM_TOTAL>>>(px, wkv, bkv, kvbuf, 2 * DIMC);
    gemm_hmma_kernel<<<152, 512, SM_TOTAL>>>(px, wkv + DIMC * DIMC, bkv + DIMC,
                                             kvbuf + DIMC, 2 * DIMC);
    attn_hmma_kernel<<<BWIN, 768, AT_TOTAL>>>(qbuf, kvbuf, addt, obuf);
    gemm_hmma_kernel<<<152, 512, SM_TOTAL>>>(obuf, wp, bp, out, DIMC);
}

// round 6
// speedup vs baseline: 2.5672x; 1.2441x over previous
#include <cuda_runtime.h>
#include <cuda_fp16.h>
#include <cstdint>

// ---------------------------------------------------------------------------
// Problem constants
// ---------------------------------------------------------------------------
#define NW        192
#define BWIN      1536
#define NTOK      64
#define DIMC      192
#define HEADS     6
#define HDIM      32
#define M_TOT     (BWIN * NTOK)     // 98304
#define MTILES    (M_TOT / 128)     // 768

// scratch
__device__ float g_Q  [M_TOT * DIMC];
__device__ float g_KV [M_TOT * 2 * DIMC];
__device__ float g_O  [M_TOT * DIMC];
__device__ float g_ADD[NW * HEADS * 4096];

// ---------------------------------------------------------------------------
// helpers (fp16)
// ---------------------------------------------------------------------------
// fp32x4 -> fp16 hi + fp16 lo residual (for the static/split operand)
__device__ __forceinline__ void splitH4(float4 v, uint2& hi, uint2& lo) {
    __half h0 = __float2half_rn(v.x);
    __half h1 = __float2half_rn(v.y);
    __half h2 = __float2half_rn(v.z);
    __half h3 = __float2half_rn(v.w);
    __half l0 = __float2half_rn(v.x - __half2float(h0));
    __half l1 = __float2half_rn(v.y - __half2float(h1));
    __half l2 = __float2half_rn(v.z - __half2float(h2));
    __half l3 = __float2half_rn(v.w - __half2float(h3));
    union { __half2 h; uint32_t u; } c0, c1, c2, c3;
    c0.h = __halves2half2(h0, h1);  c1.h = __halves2half2(h2, h3);
    c2.h = __halves2half2(l0, l1);  c3.h = __halves2half2(l2, l3);
    hi.x = c0.u; hi.y = c1.u;
    lo.x = c2.u; lo.y = c3.u;
}
// fp32x4 -> packed fp16x4 (single precision level, streamed operand)
__device__ __forceinline__ uint2 cvtH4(float4 v) {
    union { __half2 h; uint32_t u; } c0, c1;
    c0.h = __halves2half2(__float2half_rn(v.x), __float2half_rn(v.y));
    c1.h = __halves2half2(__float2half_rn(v.z), __float2half_rn(v.w));
    uint2 r; r.x = c0.u; r.y = c1.u; return r;
}
__device__ __forceinline__ uint32_t cvtH2(float p0, float p1) {
    union { __half2 h; uint32_t u; } c;
    c.h = __halves2half2(__float2half_rn(p0), __float2half_rn(p1));
    return c.u;
}
// mma.sync m16n8k16 row.col f32 += f16*f16
__device__ __forceinline__ void hmma(float* d, const uint32_t* a,
                                     uint32_t b0, uint32_t b1) {
    asm volatile(
        "mma.sync.aligned.m16n8k16.row.col.f32.f16.f16.f32 "
        "{%0,%1,%2,%3}, {%4,%5,%6,%7}, {%8,%9}, {%0,%1,%2,%3};"
        : "+f"(d[0]), "+f"(d[1]), "+f"(d[2]), "+f"(d[3])
        : "r"(a[0]), "r"(a[1]), "r"(a[2]), "r"(a[3]), "r"(b0), "r"(b1));
}

// ---------------------------------------------------------------------------
// bias table: T[(w*6+h)*4096 + i] = rpb[rpi[i]*6+h] + mask[w*4096+i]
// ---------------------------------------------------------------------------
__global__ void __launch_bounds__(256)
addtable_kernel(const float* __restrict__ mask, const int* __restrict__ rpi,
                const float* __restrict__ rpb, float* __restrict__ T)
{
    int idx = blockIdx.x * 256 + threadIdx.x;
    int i   = idx & 4095;
    int wh  = idx >> 12;
    int hd  = wh % HEADS;
    int w   = wh / HEADS;
    T[idx] = rpb[rpi[i] * HEADS + hd] + mask[w * 4096 + i];
}

// ---------------------------------------------------------------------------
// HMMA GEMM: Y[M,192] = A[M,192] @ W[192,192]^T + bias   (fp16, W split hi/lo)
// 512 threads (16 warps, 4Mx4N), warp tile 32x48, persistent CTAs,
// register-prefetch double buffering. 2 HMMA per logical MMA.
// ---------------------------------------------------------------------------
#define WSTRIDE 200
#define ASTRIDE 104

#define SM_WHI   0
#define SM_WLO   (SM_WHI + 192 * WSTRIDE * 2)
#define SM_A     (SM_WLO + 192 * WSTRIDE * 2)
#define SM_BIAS  (SM_A   + 128 * ASTRIDE * 2)
#define SM_TOTAL (SM_BIAS + 192 * 4)            // ~181 KB

__global__ void __launch_bounds__(512, 1)
gemm_hmma_kernel(const float* __restrict__ A, const float* __restrict__ W,
                 const float* __restrict__ bias, float* __restrict__ Y, int ldY)
{
    extern __shared__ char smem[];
    __half* whi = (__half*)(smem + SM_WHI);
    __half* wlo = (__half*)(smem + SM_WLO);
    __half* ash = (__half*)(smem + SM_A);
    float*  bss = (float*) (smem + SM_BIAS);

    const int tid  = threadIdx.x;
    const int lane = tid & 31;
    const int warp = tid >> 5;
    const int wm   = warp & 3;
    const int wn   = warp >> 2;

    for (int i = tid; i < 192 * 48; i += 512) {
        int row = i / 48;
        int k4  = (i % 48) * 4;
        float4 v = *(const float4*)(W + (size_t)row * DIMC + k4);
        uint2 hi, lo; splitH4(v, hi, lo);
        *(uint2*)(whi + row * WSTRIDE + k4) = hi;
        *(uint2*)(wlo + row * WSTRIDE + k4) = lo;
    }
    if (tid < DIMC) bss[tid] = bias[tid];
    __syncthreads();

    const int fr = lane >> 2;
    const int fc = (lane & 3) * 2;

    float4 pf[6];
    int tile = blockIdx.x;
    if (tile < MTILES) {
#pragma unroll
        for (int j = 0; j < 6; j++) {
            int i = tid + j * 512;
            int row = i / 24, c4 = (i % 24) * 4;
            pf[j] = *(const float4*)(A + (size_t)(tile * 128 + row) * DIMC + c4);
        }
    }

    for (; tile < MTILES; tile += gridDim.x) {
        float acc[2][6][4];
#pragma unroll
        for (int mi = 0; mi < 2; mi++)
#pragma unroll
            for (int nt = 0; nt < 6; nt++)
#pragma unroll
                for (int j = 0; j < 4; j++) acc[mi][nt][j] = 0.f;

#pragma unroll 1
        for (int c = 0; c < 2; c++) {
            __syncthreads();
#pragma unroll
            for (int j = 0; j < 6; j++) {
                int i = tid + j * 512;
                int row = i / 24, c4 = (i % 24) * 4;
                *(uint2*)(ash + row * ASTRIDE + c4) = cvtH4(pf[j]);
            }
            __syncthreads();

            int nc = c + 1, ntile = tile;
            if (nc == 2) { nc = 0; ntile = tile + gridDim.x; }
            if (ntile < MTILES) {
#pragma unroll
                for (int j = 0; j < 6; j++) {
                    int i = tid + j * 512;
                    int row = i / 24, c4 = (i % 24) * 4;
                    pf[j] = *(const float4*)(A + (size_t)(ntile * 128 + row) * DIMC
                                               + nc * 96 + c4);
                }
            }

#pragma unroll
            for (int ks = 0; ks < 6; ks++) {
                const int kk = ks * 16;
                uint32_t fa[2][4];
#pragma unroll
                for (int mi = 0; mi < 2; mi++) {
                    int r0 = wm * 32 + mi * 16 + fr;
                    const char* ba = (const char*)ash;
                    fa[mi][0] = *(const uint32_t*)(ba + (r0     * ASTRIDE + kk + fc    ) * 2);
                    fa[mi][1] = *(const uint32_t*)(ba + ((r0+8) * ASTRIDE + kk + fc    ) * 2);
                    fa[mi][2] = *(const uint32_t*)(ba + (r0     * ASTRIDE + kk + fc + 8) * 2);
                    fa[mi][3] = *(const uint32_t*)(ba + ((r0+8) * ASTRIDE + kk + fc + 8) * 2);
                }
                const int kg = c * 96 + kk + fc;
#pragma unroll
                for (int nt = 0; nt < 6; nt++) {
                    int nrow = wn * 48 + nt * 8 + fr;
                    uint32_t ob0 = (uint32_t)((nrow * WSTRIDE + kg    ) * 2);
                    uint32_t ob1 = (uint32_t)((nrow * WSTRIDE + kg + 8) * 2);
                    uint32_t bh0 = *(const uint32_t*)((const char*)whi + ob0);
                    uint32_t bh1 = *(const uint32_t*)((const char*)whi + ob1);
                    uint32_t bl0 = *(const uint32_t*)((const char*)wlo + ob0);
                    uint32_t bl1 = *(const uint32_t*)((const char*)wlo + ob1);
#pragma unroll
                    for (int mi = 0; mi < 2; mi++) {
                        hmma(acc[mi][nt], fa[mi], bh0, bh1);
                        hmma(acc[mi][nt], fa[mi], bl0, bl1);
                    }
                }
            }
        }

#pragma unroll
        for (int mi = 0; mi < 2; mi++) {
            int row = tile * 128 + wm * 32 + mi * 16 + fr;
#pragma unroll
            for (int nt = 0; nt < 6; nt++) {
                int col = wn * 48 + nt * 8 + fc;
                float2 bv = *(const float2*)&bss[col];
                float2 r0, r1;
                r0.x = acc[mi][nt][0] + bv.x;  r0.y = acc[mi][nt][1] + bv.y;
                r1.x = acc[mi][nt][2] + bv.x;  r1.y = acc[mi][nt][3] + bv.y;
                *(float2*)&Y[(size_t)row       * ldY + col] = r0;
                *(float2*)&Y[(size_t)(row + 8) * ldY + col] = r1;
            }
        }
    }
}

// ---------------------------------------------------------------------------
// HMMA attention: one block per window, 768 threads, 1 (head,mtile) per warp.
// K and Vt split hi/lo fp16 in smem; Q and P single fp16.
// ---------------------------------------------------------------------------
#define KSTR 200
#define VSTR 72

#define AT_KH 0
#define AT_KL (AT_KH + 64 * KSTR * 2)
#define AT_VH (AT_KL + 64 * KSTR * 2)
#define AT_VL (AT_VH + 192 * VSTR * 2)
#define AT_TOTAL (AT_VL + 192 * VSTR * 2)    // 106496 B

__global__ void __launch_bounds__(768, 1)
attn_hmma_kernel(const float* __restrict__ Q, const float* __restrict__ KV,
                 const float* __restrict__ ADDT, float* __restrict__ O)
{
    extern __shared__ char smem[];
    __half* kh = (__half*)(smem + AT_KH);
    __half* kl = (__half*)(smem + AT_KL);
    __half* vh = (__half*)(smem + AT_VH);
    __half* vl = (__half*)(smem + AT_VL);

    const int b   = blockIdx.x;
    const int w   = b % NW;
    const int tid = threadIdx.x;

    // ---- convert K (split), V transposed (split) into smem ----
    for (int i = tid; i < 64 * 48; i += 768) {
        int row = i / 48, c4 = (i % 48) * 4;
        const float* base = KV + (size_t)(b * 64 + row) * (2 * DIMC);
        float4 v = *(const float4*)(base + c4);
        uint2 hi, lo; splitH4(v, hi, lo);
        *(uint2*)(kh + row * KSTR + c4) = hi;
        *(uint2*)(kl + row * KSTR + c4) = lo;

        float4 vv = *(const float4*)(base + DIMC + c4);
        float vals[4] = {vv.x, vv.y, vv.z, vv.w};
#pragma unroll
        for (int j = 0; j < 4; j++) {
            __half h = __float2half_rn(vals[j]);
            __half l = __float2half_rn(vals[j] - __half2float(h));
            vh[(c4 + j) * VSTR + row] = h;
            vl[(c4 + j) * VSTR + row] = l;
        }
    }
    __syncthreads();

    const int warp = tid >> 5;      // 0..23
    const int lane = tid & 31;
    const int fr   = lane >> 2;
    const int fc   = (lane & 3) * 2;
    const int hd   = warp >> 2;     // head 0..5
    const int mt   = warp & 3;      // m-tile 0..3
    const int r0   = mt * 16 + fr;
    const int kb   = hd * 32;
    const float scale = 0.17677669529663687f;   // 1/sqrt(32)

    // ---- S = Q K^T ----
    float acc[8][4];
#pragma unroll
    for (int nt = 0; nt < 8; nt++)
#pragma unroll
        for (int j = 0; j < 4; j++) acc[nt][j] = 0.f;

#pragma unroll
    for (int ks = 0; ks < 2; ks++) {
        const int kk = kb + ks * 16;
        const float* q0 = Q + (size_t)(b * 64 + r0) * DIMC + kk + fc;
        float2 f00 = *(const float2*)(q0);
        float2 f10 = *(const float2*)(q0 + 8 * DIMC);
        float2 f01 = *(const float2*)(q0 + 8);
        float2 f11 = *(const float2*)(q0 + 8 * DIMC + 8);
        uint32_t ah[4];
        ah[0] = cvtH2(f00.x * scale, f00.y * scale);
        ah[1] = cvtH2(f10.x * scale, f10.y * scale);
        ah[2] = cvtH2(f01.x * scale, f01.y * scale);
        ah[3] = cvtH2(f11.x * scale, f11.y * scale);
#pragma unroll
        for (int nt = 0; nt < 8; nt++) {
            int nr = nt * 8 + fr;
            uint32_t bh0 = *(const uint32_t*)(kh + nr * KSTR + kk + fc);
            uint32_t bh1 = *(const uint32_t*)(kh + nr * KSTR + kk + 8 + fc);
            uint32_t bl0 = *(const uint32_t*)(kl + nr * KSTR + kk + fc);
            uint32_t bl1 = *(const uint32_t*)(kl + nr * KSTR + kk + 8 + fc);
            hmma(acc[nt], ah, bh0, bh1);
            hmma(acc[nt], ah, bl0, bl1);
        }
    }

    // ---- add bias+mask table ----
    const float* T = ADDT + ((size_t)(w * HEADS + hd)) * 4096;
#pragma unroll
    for (int nt = 0; nt < 8; nt++) {
        int cc = nt * 8 + fc;
        float2 t0 = *(const float2*)(T + (r0    ) * 64 + cc);
        float2 t1 = *(const float2*)(T + (r0 + 8) * 64 + cc);
        acc[nt][0] += t0.x;  acc[nt][1] += t0.y;
        acc[nt][2] += t1.x;  acc[nt][3] += t1.y;
    }

    // ---- fragment softmax ----
    float m0 = -1e30f, m1 = -1e30f;
#pragma unroll
    for (int nt = 0; nt < 8; nt++) {
        m0 = fmaxf(m0, fmaxf(acc[nt][0], acc[nt][1]));
        m1 = fmaxf(m1, fmaxf(acc[nt][2], acc[nt][3]));
    }
    m0 = fmaxf(m0, __shfl_xor_sync(0xffffffffu, m0, 1));
    m0 = fmaxf(m0, __shfl_xor_sync(0xffffffffu, m0, 2));
    m1 = fmaxf(m1, __shfl_xor_sync(0xffffffffu, m1, 1));
    m1 = fmaxf(m1, __shfl_xor_sync(0xffffffffu, m1, 2));

    float s0 = 0.f, s1 = 0.f;
#pragma unroll
    for (int nt = 0; nt < 8; nt++) {
        acc[nt][0] = __expf(acc[nt][0] - m0);  s0 += acc[nt][0];
        acc[nt][1] = __expf(acc[nt][1] - m0);  s0 += acc[nt][1];
        acc[nt][2] = __expf(acc[nt][2] - m1);  s1 += acc[nt][2];
        acc[nt][3] = __expf(acc[nt][3] - m1);  s1 += acc[nt][3];
    }
    s0 += __shfl_xor_sync(0xffffffffu, s0, 1);
    s0 += __shfl_xor_sync(0xffffffffu, s0, 2);
    s1 += __shfl_xor_sync(0xffffffffu, s1, 1);
    s1 += __shfl_xor_sync(0xffffffffu, s1, 2);
    float i0 = 1.f / s0, i1 = 1.f / s1;

    // ---- repack P (single fp16) into A-operand fragments ----
    uint32_t ph[4][4];
#pragma unroll
    for (int kt = 0; kt < 4; kt++) {
        ph[kt][0] = cvtH2(acc[2*kt  ][0] * i0, acc[2*kt  ][1] * i0);
        ph[kt][1] = cvtH2(acc[2*kt  ][2] * i1, acc[2*kt  ][3] * i1);
        ph[kt][2] = cvtH2(acc[2*kt+1][0] * i0, acc[2*kt+1][1] * i0);
        ph[kt][3] = cvtH2(acc[2*kt+1][2] * i1, acc[2*kt+1][3] * i1);
    }

    // ---- O = P V ----
    float oacc[4][4];
#pragma unroll
    for (int dt = 0; dt < 4; dt++)
#pragma unroll
        for (int j = 0; j < 4; j++) oacc[dt][j] = 0.f;

#pragma unroll
    for (int kt = 0; kt < 4; kt++) {
        const int tk = kt * 16 + fc;
#pragma unroll
        for (int dt = 0; dt < 4; dt++) {
            int dr = kb + dt * 8 + fr;
            uint32_t bh0 = *(const uint32_t*)(vh + dr * VSTR + tk);
            uint32_t bh1 = *(const uint32_t*)(vh + dr * VSTR + tk + 8);
            uint32_t bl0 = *(const uint32_t*)(vl + dr * VSTR + tk);
            uint32_t bl1 = *(const uint32_t*)(vl + dr * VSTR + tk + 8);
            hmma(oacc[dt], ph[kt], bh0, bh1);
            hmma(oacc[dt], ph[kt], bl0, bl1);
        }
    }

    // ---- store O ----
#pragma unroll
    for (int dt = 0; dt < 4; dt++) {
        int col = kb + dt * 8 + fc;
        float2 o0, o1;
        o0.x = oacc[dt][0];  o0.y = oacc[dt][1];
        o1.x = oacc[dt][2];  o1.y = oacc[dt][3];
        *(float2*)(O + (size_t)(b * 64 + r0    ) * DIMC + col) = o0;
        *(float2*)(O + (size_t)(b * 64 + r0 + 8) * DIMC + col) = o1;
    }
}

// ---------------------------------------------------------------------------
// launcher
// ---------------------------------------------------------------------------
extern "C" void kernel_launch(void* const* d_in, const int* in_sizes, int n_in,
                              void* d_out, int out_size)
{
    const float* x    = (const float*)d_in[0];
    const float* px   = (const float*)d_in[1];
    const float* mask = (const float*)d_in[2];
    const int*   rpi  = (const int*)  d_in[3];
    const float* rpb  = (const float*)d_in[4];
    const float* wq   = (const float*)d_in[5];
    const float* bq   = (const float*)d_in[6];
    const float* wkv  = (const float*)d_in[7];
    const float* bkv  = (const float*)d_in[8];
    const float* wp   = (const float*)d_in[9];
    const float* bp   = (const float*)d_in[10];
    float* out = (float*)d_out;

    float *qbuf, *kvbuf, *obuf, *addt;
    cudaGetSymbolAddress((void**)&qbuf,  g_Q);
    cudaGetSymbolAddress((void**)&kvbuf, g_KV);
    cudaGetSymbolAddress((void**)&obuf,  g_O);
    cudaGetSymbolAddress((void**)&addt,  g_ADD);

    cudaFuncSetAttribute(gemm_hmma_kernel,
                         cudaFuncAttributeMaxDynamicSharedMemorySize, SM_TOTAL);
    cudaFuncSetAttribute(attn_hmma_kernel,
                         cudaFuncAttributeMaxDynamicSharedMemorySize, AT_TOTAL);

    addtable_kernel<<<NW * HEADS * 4096 / 256, 256>>>(mask, rpi, rpb, addt);

    gemm_hmma_kernel<<<152, 512, SM_TOTAL>>>(x, wq, bq, qbuf, DIMC);
    gemm_hmma_kernel<<<152, 512, SM_TOTAL>>>(px, wkv, bkv, kvbuf, 2 * DIMC);
    gemm_hmma_kernel<<<152, 512, SM_TOTAL>>>(px, wkv + DIMC * DIMC, bkv + DIMC,
                                             kvbuf + DIMC, 2 * DIMC);
    attn_hmma_kernel<<<BWIN, 768, AT_TOTAL>>>(qbuf, kvbuf, addt, obuf);
    gemm_hmma_kernel<<<152, 512, SM_TOTAL>>>(obuf, wp, bp, out, DIMC);
}